// round 2
// baseline (speedup 1.0000x reference)
#include <cuda_runtime.h>
#include <math.h>

// ---------------------------------------------------------------------------
// ConsistencyLoss: kl = sum_{B,7} T[idx]*(log T[idx] - log(softmax(x)+eps)) / B
//   idx = target in {0,1,2} ? target : 3
// Inputs (metadata order): [0] fatigue_logits (UNUSED), [1] emotion_logits
// [B,7] f32, [2] fatigue_targets [B] (int32 — JAX default x64-disabled).
// Output: 1 float.
// ---------------------------------------------------------------------------

struct Params {
    float t[4][7];   // normalized target rows
    float c[4];      // sum_j t*log(t) per row
};

__device__ double g_acc;

__global__ void init_acc_kernel() { g_acc = 0.0; }

__global__ void __launch_bounds__(256)
kl_main_kernel(const float* __restrict__ logits,
               const int*   __restrict__ tgt,
               int nrows, Params P)
{
    __shared__ float sh_t[4][7];
    __shared__ float sh_c[4];
    __shared__ float sh_red[8];

    const int tid = threadIdx.x;
    if (tid < 28) sh_t[tid / 7][tid % 7] = P.t[tid / 7][tid % 7];
    if (tid < 4)  sh_c[tid] = P.c[tid];
    __syncthreads();

    const long long gthread = (long long)blockIdx.x * blockDim.x + tid;
    const long long r0 = gthread * 4;
    const float eps = 1e-8f;
    float sum = 0.0f;

    if (r0 + 4 <= (long long)nrows) {
        // 4 rows = 28 floats = 7 aligned float4 loads (112B, fully coalesced)
        float4 f[7];
        const float4* lp = (const float4*)(logits + r0 * 7);
        #pragma unroll
        for (int i = 0; i < 7; i++) f[i] = lp[i];

        // 4 int32 targets = one aligned int4 load
        const int4 tv4 = *(const int4*)(tgt + r0);
        const int tvs[4] = {tv4.x, tv4.y, tv4.z, tv4.w};

        const float* ff = (const float*)f;   // 28 floats row-major
        #pragma unroll
        for (int k = 0; k < 4; k++) {
            float x[7];
            #pragma unroll
            for (int j = 0; j < 7; j++) x[j] = ff[k * 7 + j];

            float m = x[0];
            #pragma unroll
            for (int j = 1; j < 7; j++) m = fmaxf(m, x[j]);

            float e[7], s = 0.0f;
            #pragma unroll
            for (int j = 0; j < 7; j++) { e[j] = __expf(x[j] - m); s += e[j]; }
            const float inv = __fdividef(1.0f, s);

            const int t = tvs[k];
            const int idx = (t >= 0 && t <= 2) ? t : 3;

            float dot = 0.0f;
            #pragma unroll
            for (int j = 0; j < 7; j++) {
                const float li = __logf(fmaf(e[j], inv, eps));   // log(p + eps)
                dot = fmaf(sh_t[idx][j], li, dot);
            }
            sum += sh_c[idx] - dot;
        }
    } else if (r0 < (long long)nrows) {
        // scalar tail (B=4M is divisible by 4, but stay generic)
        for (long long r = r0; r < (long long)nrows; r++) {
            float x[7];
            #pragma unroll
            for (int j = 0; j < 7; j++) x[j] = logits[r * 7 + j];
            float m = x[0];
            #pragma unroll
            for (int j = 1; j < 7; j++) m = fmaxf(m, x[j]);
            float e[7], s = 0.0f;
            #pragma unroll
            for (int j = 0; j < 7; j++) { e[j] = __expf(x[j] - m); s += e[j]; }
            const float inv = __fdividef(1.0f, s);
            const int t = tgt[r];
            const int idx = (t >= 0 && t <= 2) ? t : 3;
            float dot = 0.0f;
            #pragma unroll
            for (int j = 0; j < 7; j++) {
                const float li = __logf(fmaf(e[j], inv, eps));
                dot = fmaf(sh_t[idx][j], li, dot);
            }
            sum += sh_c[idx] - dot;
        }
    }

    // ---- block reduction: warp shuffle -> shared -> warp0 -> one double atomic
    const unsigned full = 0xFFFFFFFFu;
    #pragma unroll
    for (int off = 16; off > 0; off >>= 1)
        sum += __shfl_down_sync(full, sum, off);

    const int wid = tid >> 5, lane = tid & 31;
    if (lane == 0) sh_red[wid] = sum;
    __syncthreads();
    if (wid == 0) {
        float v = (lane < 8) ? sh_red[lane] : 0.0f;
        #pragma unroll
        for (int off = 4; off > 0; off >>= 1)
            v += __shfl_down_sync(full, v, off);
        if (lane == 0) atomicAdd(&g_acc, (double)v);
    }
}

__global__ void finalize_kernel(float* out, int nrows) {
    out[0] = (float)(g_acc / (double)nrows);
}

extern "C" void kernel_launch(void* const* d_in, const int* in_sizes, int n_in,
                              void* d_out, int out_size)
{
    const float* emotion = (const float*)d_in[1];   // [B,7]
    const int*   targets = (const int*)d_in[2];     // [B]
    const int nrows = in_sizes[2];

    // Host-side table precompute (mirrors reference float32 math)
    static const float TBL[4][7] = {
        {0.05f, 0.02f, 0.03f, 0.4f, 0.05f, 0.4f, 0.05f},
        {0.05f, 0.05f, 0.05f, 0.05f, 0.3f, 0.05f, 0.45f},
        {0.1f, 0.15f, 0.2f, 0.02f, 0.35f, 0.03f, 0.15f},
        {1.0f/7.0f, 1.0f/7.0f, 1.0f/7.0f, 1.0f/7.0f, 1.0f/7.0f, 1.0f/7.0f, 1.0f/7.0f},
    };
    Params P;
    for (int r = 0; r < 4; r++) {
        float tr[7], s = 0.0f;
        for (int j = 0; j < 7; j++) { tr[j] = TBL[r][j] + 1e-8f; s += tr[j]; }
        float c = 0.0f;
        for (int j = 0; j < 7; j++) {
            const float t = tr[j] / s;
            P.t[r][j] = t;
            c += t * logf(t);
        }
        P.c[r] = c;
    }

    init_acc_kernel<<<1, 1>>>();
    const int nthreads = (nrows + 3) / 4;
    const int blocks   = (nthreads + 255) / 256;
    kl_main_kernel<<<blocks, 256>>>(emotion, targets, nrows, P);
    finalize_kernel<<<1, 1>>>((float*)d_out, nrows);
}